// round 3
// baseline (speedup 1.0000x reference)
#include <cuda_runtime.h>
#include <math.h>

#define BB 4
#define CC 16
#define LLEN 1024
#define KK 5
#define TH 16
#define TW 64
#define CI_CHUNK 4
#define SROW (TW + 4)      // 68
#define SROWS (TH + 4)     // 20

// Scratch for softmax probabilities (exactly zero above the diagonal).
// 4*16*1024*1024 floats = 256 MB static device allocation (allowed; no cudaMalloc).
__device__ float g_probs[(size_t)BB * CC * LLEN * LLEN];

// ---------------------------------------------------------------------------
// Pass 1: causal softmax over the last dim. One block per row (b,c,i).
// Writes zeros for j > i so the conv pass needs no extra masking on reads.
// ---------------------------------------------------------------------------
__global__ __launch_bounds__(256) void softmax_causal_kernel(const float* __restrict__ scores) {
    const int row = blockIdx.x;                 // (b*CC + c)*LLEN + i
    const int i   = row & (LLEN - 1);
    const float* src = scores + (size_t)row * LLEN;
    float* dst = g_probs + (size_t)row * LLEN;
    const int tid = threadIdx.x;                // 256 threads, 4 elems/thread

    float v[4];
    float mx = -INFINITY;
#pragma unroll
    for (int k = 0; k < 4; k++) {
        int j = tid + k * 256;
        v[k] = (j <= i) ? src[j] : -INFINITY;
        mx = fmaxf(mx, v[k]);
    }
#pragma unroll
    for (int o = 16; o; o >>= 1) mx = fmaxf(mx, __shfl_xor_sync(0xffffffffu, mx, o));

    __shared__ float smax[8];
    __shared__ float ssum[8];
    if ((tid & 31) == 0) smax[tid >> 5] = mx;
    __syncthreads();
    mx = smax[0];
#pragma unroll
    for (int w = 1; w < 8; w++) mx = fmaxf(mx, smax[w]);

    float e[4];
    float s = 0.f;
#pragma unroll
    for (int k = 0; k < 4; k++) {
        int j = tid + k * 256;
        e[k] = (j <= i) ? __expf(v[k] - mx) : 0.f;
        s += e[k];
    }
#pragma unroll
    for (int o = 16; o; o >>= 1) s += __shfl_xor_sync(0xffffffffu, s, o);
    if ((tid & 31) == 0) ssum[tid >> 5] = s;
    __syncthreads();
    s = ssum[0];
#pragma unroll
    for (int w = 1; w < 8; w++) s += ssum[w];

    const float inv = 1.0f / s;
#pragma unroll
    for (int k = 0; k < 4; k++) dst[tid + k * 256] = e[k] * inv;
}

// ---------------------------------------------------------------------------
// Pass 2: 5x5 dense-channel conv + bias + causal zero-mask.
// Tile: 16 rows x 64 cols per block per batch, all 16 output channels.
// Thread = 8 output channels x 8 contiguous pixels (64 fp32 accumulators).
// Weights staged in smem as [ci][tap][co] -> broadcast LDS.128 per warp
// (co-group is warp-uniform by construction). Input rows staged in 12
// registers per (ci,ki), reused across the 5 kj shifts and all 8 co.
// ~1.07 issue slots per MAC -> FMA-pipe bound.
// Tiles entirely above the diagonal skip compute and just write zeros
// (d_out is poisoned, so every element must be written).
// ---------------------------------------------------------------------------
__global__ __launch_bounds__(256, 2) void conv_causal_kernel(
        const float* __restrict__ weight,   // [co][ci][ki][kj], 16*16*5*5
        const float* __restrict__ bias,     // [16]
        float* __restrict__ out)            // [b][co][i][j]
{
    const int cjt = blockIdx.x;             // 0..15  column tile
    const int rit = blockIdx.y;             // 0..63  row tile
    const int b   = blockIdx.z;             // 0..3
    const int i0  = rit * TH;
    const int jt0 = cjt * TW;

    const int tid = threadIdx.x;
    const int cg  = tid >> 7;               // 0/1 -> co 0-7 / 8-15 (warp-uniform)
    const int pg  = tid & 127;
    const int r   = pg >> 3;                // 0..15 tile row
    const int j0  = (pg & 7) * 8;           // 0,8,..,56 tile col group
    const int co_base = cg * 8;

    float acc[8][8];
#pragma unroll
    for (int c = 0; c < 8; c++)
#pragma unroll
        for (int p = 0; p < 8; p++) acc[c][p] = 0.f;

    const bool tile_causal = (jt0 <= i0 + TH - 1);

    __shared__ __align__(16) float s_w[CC * 25 * 16];              // 25.6 KB
    __shared__ __align__(16) float s_in[CI_CHUNK * SROWS * SROW];  // 21.8 KB

    if (tile_causal) {
        // Stage weights, re-laid-out so co is innermost (vectorizable, broadcast).
        for (int t = tid; t < CC * 25 * 16; t += 256) {
            int co  = t & 15;
            int tap = (t >> 4) % 25;
            int ci  = t / (16 * 25);
            s_w[t] = weight[(co * CC + ci) * 25 + tap];
        }

        const float* pin_base = s_in + r * SROW + j0;
        const float* pw_base  = s_w + co_base;

        for (int cc = 0; cc < CC; cc += CI_CHUNK) {
            __syncthreads();  // previous chunk fully consumed (also fences s_w writes)
            // Load input halo tile for CI_CHUNK channels (zero-pad OOB).
            for (int t = tid; t < CI_CHUNK * SROWS * SROW; t += 256) {
                int ci  = t / (SROWS * SROW);
                int rem = t - ci * (SROWS * SROW);
                int lr  = rem / SROW;
                int lc  = rem - lr * SROW;
                int gi  = i0 - 2 + lr;
                int gj  = jt0 - 2 + lc;
                float val = 0.f;
                if ((unsigned)gi < LLEN && (unsigned)gj < LLEN)
                    val = g_probs[((size_t)((b * CC + cc + ci) * LLEN) + gi) * LLEN + gj];
                s_in[t] = val;
            }
            __syncthreads();

#pragma unroll 1
            for (int ci = 0; ci < CI_CHUNK; ci++) {
                const float* wci = pw_base + (cc + ci) * 400;
                const float* ici = pin_base + ci * (SROWS * SROW);
#pragma unroll 1
                for (int ki = 0; ki < 5; ki++) {
                    float x[12];
                    const float* rp = ici + ki * SROW;
#pragma unroll
                    for (int t = 0; t < 12; t++) x[t] = rp[t];
                    const float* wk = wci + ki * 80;  // ki*5 taps * 16 co
#pragma unroll
                    for (int kj = 0; kj < 5; kj++) {
                        float4 wA = *(const float4*)(wk + kj * 16);
                        float4 wB = *(const float4*)(wk + kj * 16 + 4);
#pragma unroll
                        for (int p = 0; p < 8; p++) {
                            float xv = x[p + kj];
                            acc[0][p] = fmaf(wA.x, xv, acc[0][p]);
                            acc[1][p] = fmaf(wA.y, xv, acc[1][p]);
                            acc[2][p] = fmaf(wA.z, xv, acc[2][p]);
                            acc[3][p] = fmaf(wA.w, xv, acc[3][p]);
                            acc[4][p] = fmaf(wB.x, xv, acc[4][p]);
                            acc[5][p] = fmaf(wB.y, xv, acc[5][p]);
                            acc[6][p] = fmaf(wB.z, xv, acc[6][p]);
                            acc[7][p] = fmaf(wB.w, xv, acc[7][p]);
                        }
                    }
                }
            }
        }
    }

    // Store: bias + causal mask. Non-causal tiles fall through with acc==0.
    const int ig = i0 + r;
    const int jg = jt0 + j0;
#pragma unroll
    for (int c = 0; c < 8; c++) {
        float bv = bias[co_base + c];
        float o[8];
#pragma unroll
        for (int p = 0; p < 8; p++)
            o[p] = (jg + p <= ig) ? (acc[c][p] + bv) : 0.f;
        float* op = out + ((size_t)((b * CC + co_base + c) * LLEN) + ig) * LLEN + jg;
        *(float4*)op       = make_float4(o[0], o[1], o[2], o[3]);
        *(float4*)(op + 4) = make_float4(o[4], o[5], o[6], o[7]);
    }
}

// ---------------------------------------------------------------------------
// Launch
// ---------------------------------------------------------------------------
extern "C" void kernel_launch(void* const* d_in, const int* in_sizes, int n_in,
                              void* d_out, int out_size) {
    const float* scores = (const float*)d_in[0];  // [4,16,1024,1024]
    const float* weight = (const float*)d_in[1];  // [16,16,5,5]
    const float* bias   = (const float*)d_in[2];  // [16]
    float* out = (float*)d_out;

    softmax_causal_kernel<<<BB * CC * LLEN, 256>>>(scores);

    dim3 grid(LLEN / TW, LLEN / TH, BB);
    conv_causal_kernel<<<grid, 256>>>(weight, bias, out);
}

// round 4
// speedup vs baseline: 1.0835x; 1.0835x over previous
#include <cuda_runtime.h>
#include <math.h>

#define BB 4
#define CC 16
#define LLEN 1024
#define KK 5
#define TH 16
#define TW 64
#define CI_CHUNK 4
#define SROW 72            // 64 + 4 halo, padded to 72 for 16B-aligned LDS.128
#define SROWS (TH + 4)     // 20

// Scratch for softmax probabilities (exactly zero above the diagonal).
__device__ float g_probs[(size_t)BB * CC * LLEN * LLEN];

// ---------------------------------------------------------------------------
// Packed f32x2 helpers (sm_103a FFMA2 — ptxas never emits this on its own)
// ---------------------------------------------------------------------------
__device__ __forceinline__ void ffma2(unsigned long long& acc,
                                      unsigned long long w,
                                      unsigned long long x) {
    asm("fma.rn.f32x2 %0, %1, %2, %0;" : "+l"(acc) : "l"(w), "l"(x));
}
__device__ __forceinline__ unsigned long long pack_dup(float v) {
    unsigned long long r;
    asm("mov.b64 %0, {%1, %1};" : "=l"(r) : "f"(v));
    return r;
}
__device__ __forceinline__ void unpack2(unsigned long long v, float& lo, float& hi) {
    asm("mov.b64 {%0, %1}, %2;" : "=f"(lo), "=f"(hi) : "l"(v));
}

// ---------------------------------------------------------------------------
// Pass 1: causal softmax over the last dim. One block per row (b,c,i).
// Writes zeros for j > i so the conv pass needs no masking on reads.
// ---------------------------------------------------------------------------
__global__ __launch_bounds__(256) void softmax_causal_kernel(const float* __restrict__ scores) {
    const int row = blockIdx.x;                 // (b*CC + c)*LLEN + i
    const int i   = row & (LLEN - 1);
    const float* src = scores + (size_t)row * LLEN;
    float* dst = g_probs + (size_t)row * LLEN;
    const int tid = threadIdx.x;

    float v[4];
    float mx = -INFINITY;
#pragma unroll
    for (int k = 0; k < 4; k++) {
        int j = tid + k * 256;
        v[k] = (j <= i) ? src[j] : -INFINITY;
        mx = fmaxf(mx, v[k]);
    }
#pragma unroll
    for (int o = 16; o; o >>= 1) mx = fmaxf(mx, __shfl_xor_sync(0xffffffffu, mx, o));

    __shared__ float smax[8];
    __shared__ float ssum[8];
    if ((tid & 31) == 0) smax[tid >> 5] = mx;
    __syncthreads();
    mx = smax[0];
#pragma unroll
    for (int w = 1; w < 8; w++) mx = fmaxf(mx, smax[w]);

    float e[4];
    float s = 0.f;
#pragma unroll
    for (int k = 0; k < 4; k++) {
        int j = tid + k * 256;
        e[k] = (j <= i) ? __expf(v[k] - mx) : 0.f;
        s += e[k];
    }
#pragma unroll
    for (int o = 16; o; o >>= 1) s += __shfl_xor_sync(0xffffffffu, s, o);
    if ((tid & 31) == 0) ssum[tid >> 5] = s;
    __syncthreads();
    s = ssum[0];
#pragma unroll
    for (int w = 1; w < 8; w++) s += ssum[w];

    const float inv = 1.0f / s;
#pragma unroll
    for (int k = 0; k < 4; k++) dst[tid + k * 256] = e[k] * inv;
}

// ---------------------------------------------------------------------------
// Pass 2: 5x5 dense-channel conv + bias + causal zero-mask, FFMA2 version.
// Tile: 16 rows x 64 cols x all 16 co per block per batch.
// Thread = 4 co-PAIRS (b64 packed accumulators) x 8 contiguous pixels.
// Weights: smem [ci][tap][co], co innermost -> one 16B load = 2 co-pairs,
// warp-uniform broadcast. Inputs: 12 floats per (ci,ki) row, each duplicated
// once into (x,x) b64 and reused across 5 kj shifts and all 4 co-pairs.
// Per (ci,ki): 3 LDS.128 + 12 packs + 5*(2 LDS.128 + 32 FFMA2) = 185 slots
// for 640 MACs (vs ~333 slots scalar) -> ~1.7x issue reduction.
// ---------------------------------------------------------------------------
__global__ __launch_bounds__(256, 2) void conv_causal_kernel(
        const float* __restrict__ weight,   // [co][ci][ki][kj], 16*16*5*5
        const float* __restrict__ bias,     // [16]
        float* __restrict__ out)            // [b][co][i][j]
{
    const int cjt = blockIdx.x;             // 0..15  column tile
    const int rit = blockIdx.y;             // 0..63  row tile
    const int b   = blockIdx.z;             // 0..3
    const int i0  = rit * TH;
    const int jt0 = cjt * TW;

    const int tid = threadIdx.x;
    const int cg  = tid >> 7;               // 0/1 -> co 0-7 / 8-15 (warp-uniform)
    const int pg  = tid & 127;
    const int r   = pg >> 3;                // 0..15 tile row
    const int j0  = (pg & 7) * 8;           // 0,8,..,56 tile col group
    const int co_base = cg * 8;

    // acc[c2] holds co (co_base+2*c2, co_base+2*c2+1) packed as f32x2; 8 pixels.
    unsigned long long acc[4][8];
#pragma unroll
    for (int c = 0; c < 4; c++)
#pragma unroll
        for (int p = 0; p < 8; p++) acc[c][p] = 0ull;   // (0.0f, 0.0f)

    const bool tile_causal = (jt0 <= i0 + TH - 1);

    __shared__ __align__(16) float s_w[CC * 25 * 16];              // 25.6 KB
    __shared__ __align__(16) float s_in[CI_CHUNK * SROWS * SROW];  // 23.0 KB

    if (tile_causal) {
        // Stage weights: [ci][tap][co], co innermost.
        for (int t = tid; t < CC * 25 * 16; t += 256) {
            int co  = t & 15;
            int tap = (t >> 4) % 25;
            int ci  = t / (16 * 25);
            s_w[t] = weight[(co * CC + ci) * 25 + tap];
        }

        const float* pin_base = s_in + r * SROW + j0;
        const float* pw_base  = s_w + co_base;

        for (int cc = 0; cc < CC; cc += CI_CHUNK) {
            __syncthreads();  // previous chunk fully consumed (also fences s_w)
            // Load input halo tile for CI_CHUNK channels (zero-pad OOB & row pad).
            for (int t = tid; t < CI_CHUNK * SROWS * SROW; t += 256) {
                int ci  = t / (SROWS * SROW);
                int rem = t - ci * (SROWS * SROW);
                int lr  = rem / SROW;
                int lc  = rem - lr * SROW;
                int gi  = i0 - 2 + lr;
                int gj  = jt0 - 2 + lc;
                float val = 0.f;
                if (lc < TW + 4 && (unsigned)gi < LLEN && (unsigned)gj < LLEN)
                    val = g_probs[((size_t)((b * CC + cc + ci) * LLEN) + gi) * LLEN + gj];
                s_in[t] = val;
            }
            __syncthreads();

#pragma unroll 1
            for (int ci = 0; ci < CI_CHUNK; ci++) {
                const float* wci = pw_base + (cc + ci) * 400;
                const float* ici = pin_base + ci * (SROWS * SROW);
#pragma unroll 1
                for (int ki = 0; ki < 5; ki++) {
                    const float* rp = ici + ki * SROW;     // 16B aligned
                    float4 xa = *(const float4*)(rp);
                    float4 xb = *(const float4*)(rp + 4);
                    float4 xc = *(const float4*)(rp + 8);
                    unsigned long long pv[12];
                    pv[0]  = pack_dup(xa.x);  pv[1]  = pack_dup(xa.y);
                    pv[2]  = pack_dup(xa.z);  pv[3]  = pack_dup(xa.w);
                    pv[4]  = pack_dup(xb.x);  pv[5]  = pack_dup(xb.y);
                    pv[6]  = pack_dup(xb.z);  pv[7]  = pack_dup(xb.w);
                    pv[8]  = pack_dup(xc.x);  pv[9]  = pack_dup(xc.y);
                    pv[10] = pack_dup(xc.z);  pv[11] = pack_dup(xc.w);

                    const float* wk = wci + ki * 80;       // ki*5 taps * 16 co
#pragma unroll
                    for (int kj = 0; kj < 5; kj++) {
                        // 2 co-pairs per 16B load, both 16B aligned, warp-uniform.
                        const ulonglong2 wA = *(const ulonglong2*)(wk + kj * 16);
                        const ulonglong2 wB = *(const ulonglong2*)(wk + kj * 16 + 4);
#pragma unroll
                        for (int p = 0; p < 8; p++) {
                            const unsigned long long xv = pv[p + kj];
                            ffma2(acc[0][p], wA.x, xv);
                            ffma2(acc[1][p], wA.y, xv);
                            ffma2(acc[2][p], wB.x, xv);
                            ffma2(acc[3][p], wB.y, xv);
                        }
                    }
                }
            }
        }
    }

    // Store: bias + causal mask. Non-causal tiles fall through with acc==0.
    const int ig = i0 + r;
    const int jg = jt0 + j0;
#pragma unroll
    for (int c2 = 0; c2 < 4; c2++) {
        const int coA = co_base + 2 * c2;
        const float bA = bias[coA];
        const float bB = bias[coA + 1];
        float oA[8], oB[8];
#pragma unroll
        for (int p = 0; p < 8; p++) {
            float lo, hi;
            unpack2(acc[c2][p], lo, hi);
            const bool ok = (jg + p <= ig);
            oA[p] = ok ? (lo + bA) : 0.f;
            oB[p] = ok ? (hi + bB) : 0.f;
        }
        float* opA = out + ((size_t)((b * CC + coA) * LLEN) + ig) * LLEN + jg;
        float* opB = opA + (size_t)LLEN * LLEN;
        *(float4*)opA       = make_float4(oA[0], oA[1], oA[2], oA[3]);
        *(float4*)(opA + 4) = make_float4(oA[4], oA[5], oA[6], oA[7]);
        *(float4*)opB       = make_float4(oB[0], oB[1], oB[2], oB[3]);
        *(float4*)(opB + 4) = make_float4(oB[4], oB[5], oB[6], oB[7]);
    }
}

// ---------------------------------------------------------------------------
// Launch
// ---------------------------------------------------------------------------
extern "C" void kernel_launch(void* const* d_in, const int* in_sizes, int n_in,
                              void* d_out, int out_size) {
    const float* scores = (const float*)d_in[0];  // [4,16,1024,1024]
    const float* weight = (const float*)d_in[1];  // [16,16,5,5]
    const float* bias   = (const float*)d_in[2];  // [16]
    float* out = (float*)d_out;

    softmax_causal_kernel<<<BB * CC * LLEN, 256>>>(scores);

    dim3 grid(LLEN / TW, LLEN / TH, BB);
    conv_causal_kernel<<<grid, 256>>>(weight, bias, out);
}

// round 8
// speedup vs baseline: 1.2409x; 1.1453x over previous
#include <cuda_runtime.h>
#include <cstdint>
#include <math.h>

#define BB 4
#define CC 16
#define LLEN 1024
#define KK 5
#define TH 16
#define TW 64
#define CI_CHUNK 2
#define NCHUNK (CC / CI_CHUNK)     // 8
#define SROW 72                    // 64 + 4 halo, padded to 72 (16B-aligned rows)
#define SROWS (TH + 4)             // 20
#define CHUNK_ELEMS (CI_CHUNK * SROWS * SROW)   // 2880 floats = 11.5 KB
#define NPAIRS (CI_CHUNK * SROWS * 34)          // 8B cp.async transfers per chunk

// Scratch for softmax probabilities (exactly zero above the diagonal).
__device__ float g_probs[(size_t)BB * CC * LLEN * LLEN];

// ---------------------------------------------------------------------------
// Packed f32x2 helpers (sm_103a FFMA2 — ptxas never emits this on its own)
// ---------------------------------------------------------------------------
__device__ __forceinline__ void ffma2(unsigned long long& acc,
                                      unsigned long long w,
                                      unsigned long long x) {
    asm("fma.rn.f32x2 %0, %1, %2, %0;" : "+l"(acc) : "l"(w), "l"(x));
}
__device__ __forceinline__ unsigned long long pack_dup(float v) {
    unsigned long long r;
    asm("mov.b64 %0, {%1, %1};" : "=l"(r) : "f"(v));
    return r;
}
__device__ __forceinline__ void unpack2(unsigned long long v, float& lo, float& hi) {
    asm("mov.b64 {%0, %1}, %2;" : "=f"(lo), "=f"(hi) : "l"(v));
}

// ---------------------------------------------------------------------------
// Pass 1: causal softmax over the last dim. One block per row (b,c,i).
// Writes zeros for j > i so the conv pass needs no masking on reads.
// ---------------------------------------------------------------------------
__global__ __launch_bounds__(256) void softmax_causal_kernel(const float* __restrict__ scores) {
    const int row = blockIdx.x;                 // (b*CC + c)*LLEN + i
    const int i   = row & (LLEN - 1);
    const float* src = scores + (size_t)row * LLEN;
    float* dst = g_probs + (size_t)row * LLEN;
    const int tid = threadIdx.x;

    float v[4];
    float mx = -INFINITY;
#pragma unroll
    for (int k = 0; k < 4; k++) {
        int j = tid + k * 256;
        v[k] = (j <= i) ? src[j] : -INFINITY;
        mx = fmaxf(mx, v[k]);
    }
#pragma unroll
    for (int o = 16; o; o >>= 1) mx = fmaxf(mx, __shfl_xor_sync(0xffffffffu, mx, o));

    __shared__ float smax[8];
    __shared__ float ssum[8];
    if ((tid & 31) == 0) smax[tid >> 5] = mx;
    __syncthreads();
    mx = smax[0];
#pragma unroll
    for (int w = 1; w < 8; w++) mx = fmaxf(mx, smax[w]);

    float e[4];
    float s = 0.f;
#pragma unroll
    for (int k = 0; k < 4; k++) {
        int j = tid + k * 256;
        e[k] = (j <= i) ? __expf(v[k] - mx) : 0.f;
        s += e[k];
    }
#pragma unroll
    for (int o = 16; o; o >>= 1) s += __shfl_xor_sync(0xffffffffu, s, o);
    if ((tid & 31) == 0) ssum[tid >> 5] = s;
    __syncthreads();
    s = ssum[0];
#pragma unroll
    for (int w = 1; w < 8; w++) s += ssum[w];

    const float inv = 1.0f / s;
#pragma unroll
    for (int k = 0; k < 4; k++) dst[tid + k * 256] = e[k] * inv;
}

// ---------------------------------------------------------------------------
// cp.async staging of one CI_CHUNK input halo tile (8B transfers, zfill OOB).
// Register-free async copy: keeps occupancy at 2 CTAs/SM while hiding DRAM
// latency under the previous chunk's FFMA2 work.
// gj is always even (jt0 even, halo -2), so no transfer straddles the 0/1024
// row boundary: every 8B pair is fully in-range or fully zero-filled.
// ---------------------------------------------------------------------------
__device__ __forceinline__ void issue_chunk_loads(
        const float* __restrict__ probs_b,   // g_probs + batch plane base
        int i0, int jt0, int cc, float* sbuf, int tid)
{
    const unsigned int sbase = (unsigned int)__cvta_generic_to_shared(sbuf);
#pragma unroll
    for (int it = 0; it < (NPAIRS + 255) / 256; it++) {
        int e = tid + it * 256;
        if (e < NPAIRS) {
            int ci  = e / (SROWS * 34);
            int rem = e - ci * (SROWS * 34);
            int lr  = rem / 34;
            int m   = rem - lr * 34;
            int gi  = i0 - 2 + lr;
            int gj  = jt0 - 2 + 2 * m;
            bool ok = ((unsigned)gi < LLEN) && ((unsigned)gj < LLEN);
            const float* src = ok
                ? probs_b + ((size_t)(cc + ci) * LLEN + gi) * LLEN + gj
                : probs_b;                           // clamped valid addr, size 0
            unsigned int dst = sbase + (unsigned int)(((ci * SROWS + lr) * SROW + 2 * m) * 4);
            int sz = ok ? 8 : 0;
            asm volatile("cp.async.ca.shared.global [%0], [%1], 8, %2;"
                         :: "r"(dst), "l"(src), "r"(sz));
        }
    }
}

// ---------------------------------------------------------------------------
// Pass 2: 5x5 dense-channel conv + bias + causal zero-mask.
// FFMA2 compute (co-pairs packed f32x2) + cp.async double-buffered input.
// Tile: 16 rows x 64 cols x 16 co per block per batch.
// Thread = 4 co-pairs x 8 contiguous pixels (32 b64 accumulators).
// ---------------------------------------------------------------------------
__global__ __launch_bounds__(256, 2) void conv_causal_kernel(
        const float* __restrict__ weight,   // [co][ci][ki][kj], 16*16*5*5
        const float* __restrict__ bias,     // [16]
        float* __restrict__ out)            // [b][co][i][j]
{
    const int cjt = blockIdx.x;             // 0..15  column tile
    const int rit = blockIdx.y;             // 0..63  row tile
    const int b   = blockIdx.z;             // 0..3
    const int i0  = rit * TH;
    const int jt0 = cjt * TW;

    const int tid = threadIdx.x;
    const int cg  = tid >> 7;               // 0/1 -> co 0-7 / 8-15 (warp-uniform)
    const int pg  = tid & 127;
    const int r   = pg >> 3;                // 0..15 tile row
    const int j0  = (pg & 7) * 8;           // 0,8,..,56 tile col group
    const int co_base = cg * 8;

    unsigned long long acc[4][8];
#pragma unroll
    for (int c = 0; c < 4; c++)
#pragma unroll
        for (int p = 0; p < 8; p++) acc[c][p] = 0ull;

    const bool tile_causal = (jt0 <= i0 + TH - 1);

    __shared__ __align__(16) float s_w[CC * 25 * 16];          // 25.6 KB
    __shared__ __align__(16) float s_in[2 * CHUNK_ELEMS];      // 2 x 11.5 KB

    if (tile_causal) {
        // Stage weights: [ci][tap][co], co innermost (broadcast LDS.128).
        for (int t = tid; t < CC * 25 * 16; t += 256) {
            int co  = t & 15;
            int tap = (t >> 4) % 25;
            int ci  = t / (16 * 25);
            s_w[t] = weight[(co * CC + ci) * 25 + tap];
        }

        const float* probs_b = g_probs + (size_t)b * CC * LLEN * LLEN;
        const float* pw_base = s_w + co_base;

        // Prologue: stage chunk 0.
        issue_chunk_loads(probs_b, i0, jt0, 0, s_in, tid);
        asm volatile("cp.async.commit_group;" ::: "memory");

#pragma unroll 1
        for (int c = 0; c < NCHUNK; c++) {
            float* cur = s_in + (c & 1) * CHUNK_ELEMS;
            if (c < NCHUNK - 1) {
                issue_chunk_loads(probs_b, i0, jt0, (c + 1) * CI_CHUNK,
                                  s_in + ((c + 1) & 1) * CHUNK_ELEMS, tid);
                asm volatile("cp.async.commit_group;" ::: "memory");
                asm volatile("cp.async.wait_group 1;" ::: "memory");
            } else {
                asm volatile("cp.async.wait_group 0;" ::: "memory");
            }
            __syncthreads();   // chunk c visible to all (also fences s_w on c==0)

            const float* pin_base = cur + r * SROW + j0;
#pragma unroll 1
            for (int ci = 0; ci < CI_CHUNK; ci++) {
                const float* wci = pw_base + (c * CI_CHUNK + ci) * 400;
                const float* ici = pin_base + ci * (SROWS * SROW);
#pragma unroll 1
                for (int ki = 0; ki < 5; ki++) {
                    const float* rp = ici + ki * SROW;     // 16B aligned
                    float4 xa = *(const float4*)(rp);
                    float4 xb = *(const float4*)(rp + 4);
                    float4 xc = *(const float4*)(rp + 8);
                    unsigned long long pv[12];
                    pv[0]  = pack_dup(xa.x);  pv[1]  = pack_dup(xa.y);
                    pv[2]  = pack_dup(xa.z);  pv[3]  = pack_dup(xa.w);
                    pv[4]  = pack_dup(xb.x);  pv[5]  = pack_dup(xb.y);
                    pv[6]  = pack_dup(xb.z);  pv[7]  = pack_dup(xb.w);
                    pv[8]  = pack_dup(xc.x);  pv[9]  = pack_dup(xc.y);
                    pv[10] = pack_dup(xc.z);  pv[11] = pack_dup(xc.w);

                    const float* wk = wci + ki * 80;       // ki*5 taps * 16 co
#pragma unroll
                    for (int kj = 0; kj < 5; kj++) {
                        const ulonglong2 wA = *(const ulonglong2*)(wk + kj * 16);
                        const ulonglong2 wB = *(const ulonglong2*)(wk + kj * 16 + 4);
#pragma unroll
                        for (int p = 0; p < 8; p++) {
                            const unsigned long long xv = pv[p + kj];
                            ffma2(acc[0][p], wA.x, xv);
                            ffma2(acc[1][p], wA.y, xv);
                            ffma2(acc[2][p], wB.x, xv);
                            ffma2(acc[3][p], wB.y, xv);
                        }
                    }
                }
            }
            __syncthreads();   // all reads of cur done before iter c+1 overwrites it
        }
    }

    // Store: bias + causal mask. Non-causal tiles fall through with acc==0.
    const int ig = i0 + r;
    const int jg = jt0 + j0;
#pragma unroll
    for (int c2 = 0; c2 < 4; c2++) {
        const int coA = co_base + 2 * c2;
        const float bA = bias[coA];
        const float bB = bias[coA + 1];
        float oA[8], oB[8];
#pragma unroll
        for (int p = 0; p < 8; p++) {
            float lo, hi;
            unpack2(acc[c2][p], lo, hi);
            const bool ok = (jg + p <= ig);
            oA[p] = ok ? (lo + bA) : 0.f;
            oB[p] = ok ? (hi + bB) : 0.f;
        }
        float* opA = out + ((size_t)((b * CC + coA) * LLEN) + ig) * LLEN + jg;
        float* opB = opA + (size_t)LLEN * LLEN;
        *(float4*)opA       = make_float4(oA[0], oA[1], oA[2], oA[3]);
        *(float4*)(opA + 4) = make_float4(oA[4], oA[5], oA[6], oA[7]);
        *(float4*)opB       = make_float4(oB[0], oB[1], oB[2], oB[3]);
        *(float4*)(opB + 4) = make_float4(oB[4], oB[5], oB[6], oB[7]);
    }
}

// ---------------------------------------------------------------------------
// Launch
// ---------------------------------------------------------------------------
extern "C" void kernel_launch(void* const* d_in, const int* in_sizes, int n_in,
                              void* d_out, int out_size) {
    const float* scores = (const float*)d_in[0];  // [4,16,1024,1024]
    const float* weight = (const float*)d_in[1];  // [16,16,5,5]
    const float* bias   = (const float*)d_in[2];  // [16]
    float* out = (float*)d_out;

    softmax_causal_kernel<<<BB * CC * LLEN, 256>>>(scores);

    dim3 grid(LLEN / TW, LLEN / TH, BB);
    conv_causal_kernel<<<grid, 256>>>(weight, bias, out);
}